// round 1
// baseline (speedup 1.0000x reference)
#include <cuda_runtime.h>
#include <cuda_bf16.h>
#include <cstdint>
#include <cmath>

// Problem constants
static constexpr int Bn   = 32;
static constexpr int Tn   = 2048;
static constexpr int DIN  = 1024;
static constexpr int H1   = 512;
static constexpr int H2   = 32;
static constexpr int Mrows = Bn * Tn;   // 65536

// Device scratch (allowed: __device__ globals, no runtime alloc)
__device__ __nv_bfloat16 g_w1b[DIN * H1];   // 1 MB
__device__ __nv_bfloat16 g_w2b[H1 * H2];    // 32 KB
__device__ float         g_logits[Mrows];   // 256 KB

// ---------------------------------------------------------------------------
// helpers
// ---------------------------------------------------------------------------
__device__ __forceinline__ uint32_t smaddr(const void* p) {
    return (uint32_t)__cvta_generic_to_shared(p);
}
__device__ __forceinline__ void ldsm4(uint32_t addr, uint32_t& r0, uint32_t& r1,
                                      uint32_t& r2, uint32_t& r3) {
    asm volatile("ldmatrix.sync.aligned.m8n8.x4.shared.b16 {%0,%1,%2,%3}, [%4];"
                 : "=r"(r0), "=r"(r1), "=r"(r2), "=r"(r3) : "r"(addr));
}
__device__ __forceinline__ void ldsm4t(uint32_t addr, uint32_t& r0, uint32_t& r1,
                                       uint32_t& r2, uint32_t& r3) {
    asm volatile("ldmatrix.sync.aligned.m8n8.x4.trans.shared.b16 {%0,%1,%2,%3}, [%4];"
                 : "=r"(r0), "=r"(r1), "=r"(r2), "=r"(r3) : "r"(addr));
}
__device__ __forceinline__ void mma_bf16(float& c0, float& c1, float& c2, float& c3,
                                         uint32_t a0, uint32_t a1, uint32_t a2, uint32_t a3,
                                         uint32_t b0, uint32_t b1) {
    asm volatile("mma.sync.aligned.m16n8k16.row.col.f32.bf16.bf16.f32 "
                 "{%0,%1,%2,%3}, {%4,%5,%6,%7}, {%8,%9}, {%0,%1,%2,%3};"
                 : "+f"(c0), "+f"(c1), "+f"(c2), "+f"(c3)
                 : "r"(a0), "r"(a1), "r"(a2), "r"(a3), "r"(b0), "r"(b1));
}
__device__ __forceinline__ void cp16(uint32_t dst, const void* src) {
    asm volatile("cp.async.cg.shared.global [%0], [%1], 16;" :: "r"(dst), "l"(src));
}
__device__ __forceinline__ void cp_commit() { asm volatile("cp.async.commit_group;"); }
template <int N> __device__ __forceinline__ void cp_wait() {
    asm volatile("cp.async.wait_group %0;" :: "n"(N));
}

// ---------------------------------------------------------------------------
// kernel 0: convert W1/W2 fp32 -> bf16 device globals
// ---------------------------------------------------------------------------
__global__ void k_convert(const float* __restrict__ W1, const float* __restrict__ W2) {
    int g = blockIdx.x * blockDim.x + threadIdx.x;
    const int n1 = DIN * H1 / 4;    // 131072 float4 chunks
    const int n2 = H1 * H2 / 4;     // 4096
    if (g < n1) {
        float4 v = reinterpret_cast<const float4*>(W1)[g];
        __nv_bfloat162* p = reinterpret_cast<__nv_bfloat162*>(g_w1b) + g * 2;
        p[0] = __floats2bfloat162_rn(v.x, v.y);
        p[1] = __floats2bfloat162_rn(v.z, v.w);
    } else if (g - n1 < n2) {
        int h = g - n1;
        float4 v = reinterpret_cast<const float4*>(W2)[h];
        __nv_bfloat162* p = reinterpret_cast<__nv_bfloat162*>(g_w2b) + h * 2;
        p[0] = __floats2bfloat162_rn(v.x, v.y);
        p[1] = __floats2bfloat162_rn(v.z, v.w);
    }
}

// ---------------------------------------------------------------------------
// kernel 1: fused 3-layer MLP + sigmoid -> g_logits
//   block = 64 rows, 256 threads (8 warps: wm in 0..3 x 16 rows, wn in 0..1 x 64 cols)
//   smem: Xs[64][1032] bf16 | W1s[2][64][136] bf16 | W2s[128][40] bf16 | H2s[64][33] f32
// ---------------------------------------------------------------------------
static constexpr int XS_STRIDE  = 1032;                 // pad -> conflict-free ldmatrix
static constexpr int W1S_STRIDE = 136;
static constexpr int W2S_STRIDE = 40;
static constexpr int XS_BYTES   = 64 * XS_STRIDE * 2;            // 132096
static constexpr int W1S_OFF    = XS_BYTES;                      // 132096
static constexpr int W1S_BUF_B  = 64 * W1S_STRIDE * 2;           // 17408
static constexpr int W2S_OFF    = W1S_OFF + 2 * W1S_BUF_B;       // 166912
static constexpr int H2S_OFF    = W2S_OFF + 128 * W2S_STRIDE * 2; // 177152
static constexpr int SMEM_TOTAL = H2S_OFF + 64 * 33 * 4;         // 185600

__global__ void __launch_bounds__(256, 1)
k_fused(const float* __restrict__ X, const float* __restrict__ b1,
        const float* __restrict__ b2, const float* __restrict__ W3,
        const float* __restrict__ b3) {
    extern __shared__ char smem[];
    __nv_bfloat16* Xs  = reinterpret_cast<__nv_bfloat16*>(smem);
    __nv_bfloat16* W1s = reinterpret_cast<__nv_bfloat16*>(smem + W1S_OFF);
    __nv_bfloat16* W2s = reinterpret_cast<__nv_bfloat16*>(smem + W2S_OFF);
    float*         H2s = reinterpret_cast<float*>(smem + H2S_OFF);

    const int tid  = threadIdx.x;
    const int lane = tid & 31;
    const int wid  = tid >> 5;
    const int wm   = wid & 3;      // row group (16 rows)
    const int wn   = wid >> 2;     // col group (64 cols)
    const int m0   = blockIdx.x * 64;

    // ---- load X tile fp32 -> bf16 smem ----
    for (int i = tid; i < 64 * 256; i += 256) {
        int row = i >> 8, c4 = i & 255;
        float4 v = reinterpret_cast<const float4*>(X + (size_t)(m0 + row) * DIN)[c4];
        __nv_bfloat162* p = reinterpret_cast<__nv_bfloat162*>(Xs + row * XS_STRIDE + c4 * 4);
        p[0] = __floats2bfloat162_rn(v.x, v.y);
        p[1] = __floats2bfloat162_rn(v.z, v.w);
    }

    // lane->fragment address constants (ldmatrix m8n8.x4 mapping)
    const int lk   = lane & 15;
    const int lhi8 = (lane & 16) ? 8 : 0;
    const uint32_t xs_base  = smaddr(Xs)  + (uint32_t)(((wm * 16 + lk) * XS_STRIDE + lhi8) * 2);
    const uint32_t w1s_base = smaddr(W1s) + (uint32_t)((lk * W1S_STRIDE + wn * 64 + lhi8) * 2);
    const uint32_t w2s_base = smaddr(W2s) + (uint32_t)((lk * W2S_STRIDE + lhi8) * 2);

    float h2acc[4][4];
    #pragma unroll
    for (int nt = 0; nt < 4; nt++)
        #pragma unroll
        for (int q = 0; q < 4; q++) h2acc[nt][q] = 0.f;

    __syncthreads();   // Xs ready

    for (int ch = 0; ch < 4; ch++) {
        const int n0 = ch * 128;   // h1 column base of this chunk

        // per-thread layer-1 bias values for owned columns
        float2 bb[8];
        #pragma unroll
        for (int t = 0; t < 8; t++)
            bb[t] = *reinterpret_cast<const float2*>(b1 + n0 + wn * 64 + t * 8 + (lane & 3) * 2);

        float c[8][4];
        #pragma unroll
        for (int t = 0; t < 8; t++)
            #pragma unroll
            for (int q = 0; q < 4; q++) c[t][q] = 0.f;

        // preload W1 slab 0 (bf16, rows = k 0..63, cols n0..n0+127)
        {
            const __nv_bfloat16* srcb = g_w1b + n0;
            for (int i = tid; i < 1024; i += 256) {
                int r = i >> 4, seg = i & 15;
                uint32_t dst = smaddr(W1s) + (uint32_t)((r * W1S_STRIDE + seg * 8) * 2);
                cp16(dst, srcb + (size_t)r * H1 + seg * 8);
            }
            cp_commit();
        }

        for (int ks = 0; ks < 16; ks++) {
            if (ks < 15) {   // prefetch next slab into other buffer
                const __nv_bfloat16* srcb = g_w1b + (size_t)(ks + 1) * 64 * H1 + n0;
                int buf = (ks + 1) & 1;
                for (int i = tid; i < 1024; i += 256) {
                    int r = i >> 4, seg = i & 15;
                    uint32_t dst = smaddr(W1s) +
                        (uint32_t)(((buf * 64 + r) * W1S_STRIDE + seg * 8) * 2);
                    cp16(dst, srcb + (size_t)r * H1 + seg * 8);
                }
                cp_commit();
                cp_wait<1>();
            } else {
                cp_wait<0>();
            }
            __syncthreads();

            const uint32_t wbuf = w1s_base + (uint32_t)((ks & 1) * W1S_BUF_B);
            #pragma unroll
            for (int st = 0; st < 4; st++) {
                const int kglob = ks * 64 + st * 16;
                uint32_t a0, a1, a2, a3;
                ldsm4(xs_base + (uint32_t)(kglob * 2), a0, a1, a2, a3);
                uint32_t rb[4][4];
                #pragma unroll
                for (int p = 0; p < 4; p++)
                    ldsm4t(wbuf + (uint32_t)((st * 16 * W1S_STRIDE + 16 * p) * 2),
                           rb[p][0], rb[p][1], rb[p][2], rb[p][3]);
                #pragma unroll
                for (int t = 0; t < 8; t++)
                    mma_bf16(c[t][0], c[t][1], c[t][2], c[t][3],
                             a0, a1, a2, a3,
                             rb[t >> 1][(t & 1) * 2], rb[t >> 1][(t & 1) * 2 + 1]);
            }
            __syncthreads();
        }

        // load W2 chunk rows [n0, n0+128) into smem (bf16, row = 64B)
        for (int i = tid; i < 1024; i += 256) {
            int r = i >> 3, seg = i & 7;
            uint64_t v = *reinterpret_cast<const uint64_t*>(
                reinterpret_cast<const char*>(g_w2b) + ((size_t)(n0 + r) * H2 + seg * 4) * 2);
            *reinterpret_cast<uint64_t*>(
                reinterpret_cast<char*>(W2s) + r * (W2S_STRIDE * 2) + seg * 8) = v;
        }

        // bias + relu + pack layer-1 outputs directly into layer-2 A fragments:
        // two adjacent m16n8 C tiles == one m16k16 A fragment (no smem round-trip)
        uint32_t a2f[4][4];
        #pragma unroll
        for (int s = 0; s < 4; s++) {
            const int t0 = 2 * s, t1 = 2 * s + 1;
            __nv_bfloat162 h;
            h = __floats2bfloat162_rn(fmaxf(c[t0][0] + bb[t0].x, 0.f),
                                      fmaxf(c[t0][1] + bb[t0].y, 0.f));
            a2f[s][0] = *reinterpret_cast<uint32_t*>(&h);
            h = __floats2bfloat162_rn(fmaxf(c[t0][2] + bb[t0].x, 0.f),
                                      fmaxf(c[t0][3] + bb[t0].y, 0.f));
            a2f[s][1] = *reinterpret_cast<uint32_t*>(&h);
            h = __floats2bfloat162_rn(fmaxf(c[t1][0] + bb[t1].x, 0.f),
                                      fmaxf(c[t1][1] + bb[t1].y, 0.f));
            a2f[s][2] = *reinterpret_cast<uint32_t*>(&h);
            h = __floats2bfloat162_rn(fmaxf(c[t1][2] + bb[t1].x, 0.f),
                                      fmaxf(c[t1][3] + bb[t1].y, 0.f));
            a2f[s][3] = *reinterpret_cast<uint32_t*>(&h);
        }
        __syncthreads();   // W2s visible

        // layer-2 mma: A = relu(h1)[16 rows x 64 cols of this warp], B = W2 slab
        #pragma unroll
        for (int s = 0; s < 4; s++) {
            uint32_t rb2[2][4];
            #pragma unroll
            for (int p = 0; p < 2; p++)
                ldsm4t(w2s_base +
                           (uint32_t)(((wn * 64 + s * 16) * W2S_STRIDE + 16 * p) * 2),
                       rb2[p][0], rb2[p][1], rb2[p][2], rb2[p][3]);
            #pragma unroll
            for (int nt = 0; nt < 4; nt++)
                mma_bf16(h2acc[nt][0], h2acc[nt][1], h2acc[nt][2], h2acc[nt][3],
                         a2f[s][0], a2f[s][1], a2f[s][2], a2f[s][3],
                         rb2[nt >> 1][(nt & 1) * 2], rb2[nt >> 1][(nt & 1) * 2 + 1]);
        }
        __syncthreads();   // safe to overwrite W1s/W2s next chunk
    }

    // ---- combine partial H2 across wn, then layer 3 + sigmoid ----
    const int r0 = wm * 16 + (lane >> 2);
    const int cc = (lane & 3) * 2;
    if (wn == 0) {
        #pragma unroll
        for (int nt = 0; nt < 4; nt++) {
            H2s[r0 * 33 + nt * 8 + cc]           = h2acc[nt][0];
            H2s[r0 * 33 + nt * 8 + cc + 1]       = h2acc[nt][1];
            H2s[(r0 + 8) * 33 + nt * 8 + cc]     = h2acc[nt][2];
            H2s[(r0 + 8) * 33 + nt * 8 + cc + 1] = h2acc[nt][3];
        }
    }
    __syncthreads();
    if (wn == 1) {
        #pragma unroll
        for (int nt = 0; nt < 4; nt++) {
            H2s[r0 * 33 + nt * 8 + cc]           += h2acc[nt][0];
            H2s[r0 * 33 + nt * 8 + cc + 1]       += h2acc[nt][1];
            H2s[(r0 + 8) * 33 + nt * 8 + cc]     += h2acc[nt][2];
            H2s[(r0 + 8) * 33 + nt * 8 + cc + 1] += h2acc[nt][3];
        }
    }
    __syncthreads();
    if (tid < 64) {
        float acc = b3[0];
        #pragma unroll
        for (int j = 0; j < H2; j++)
            acc += (H2s[tid * 33 + j] + b2[j]) * W3[j];
        g_logits[m0 + tid] = 1.0f / (1.0f + expf(-acc));
    }
}

// ---------------------------------------------------------------------------
// kernel 2: per-sample masked bitonic sort + top-k mean (exact ref semantics)
// ---------------------------------------------------------------------------
__global__ void k_topk(const int* __restrict__ seq_len, float* __restrict__ out) {
    __shared__ float v[Tn];
    __shared__ float red[256];
    const int b = blockIdx.x;
    const int tid = threadIdx.x;
    const int sl = seq_len[b];
    const int k = sl / 16 + 1;

    for (int i = tid; i < Tn; i += 256)
        v[i] = (i < sl) ? g_logits[b * Tn + i] : -1.0f;  // below sigmoid range
    __syncthreads();

    // in-smem bitonic sort, ascending
    for (int kk = 2; kk <= Tn; kk <<= 1) {
        for (int j = kk >> 1; j > 0; j >>= 1) {
            for (int i = tid; i < Tn; i += 256) {
                int ixj = i ^ j;
                if (ixj > i) {
                    float a = v[i], c = v[ixj];
                    bool up = ((i & kk) == 0);
                    if ((a > c) == up) { v[i] = c; v[ixj] = a; }
                }
            }
            __syncthreads();
        }
    }

    // sum of k largest = v[Tn-k .. Tn-1]
    float s = 0.f;
    for (int i = Tn - k + tid; i < Tn; i += 256) s += v[i];
    red[tid] = s;
    __syncthreads();
    for (int off = 128; off > 0; off >>= 1) {
        if (tid < off) red[tid] += red[tid + off];
        __syncthreads();
    }
    if (tid == 0) out[b] = red[0] / (float)k;
}

// ---------------------------------------------------------------------------
extern "C" void kernel_launch(void* const* d_in, const int* in_sizes, int n_in,
                              void* d_out, int out_size) {
    const float* X   = (const float*)d_in[0];
    const float* W1  = (const float*)d_in[1];
    const float* b1  = (const float*)d_in[2];
    const float* W2  = (const float*)d_in[3];
    const float* b2  = (const float*)d_in[4];
    const float* W3  = (const float*)d_in[5];
    const float* b3  = (const float*)d_in[6];
    const int*   seq = (const int*)d_in[7];
    float* out = (float*)d_out;

    k_convert<<<(DIN * H1 / 4 + H1 * H2 / 4 + 255) / 256, 256>>>(W1, W2);

    cudaFuncSetAttribute(k_fused, cudaFuncAttributeMaxDynamicSharedMemorySize, SMEM_TOTAL);
    k_fused<<<Mrows / 64, 256, SMEM_TOTAL>>>(X, b1, b2, W3, b3);

    k_topk<<<Bn, 256>>>(seq, out);
}

// round 3
// speedup vs baseline: 1.4619x; 1.4619x over previous
#include <cuda_runtime.h>
#include <cuda_bf16.h>
#include <cstdint>
#include <cmath>

static constexpr int Bn = 32, Tn = 2048, DIN = 1024, H1 = 512, H2 = 32;
static constexpr int Mrows = Bn * Tn;   // 65536

// Device scratch
__device__ __nv_bfloat16 g_w1b[DIN * H1];   // W1 bf16 [1024 k][512 n]
__device__ __nv_bfloat16 g_w2b[H1 * H2];    // W2 bf16 [512 k][32 n]
__device__ float         g_logits[Mrows];

// ---------------------------------------------------------------------------
// helpers (HMMA path — sm_80-class PTX only, no arch-suffix features)
// ---------------------------------------------------------------------------
__device__ __forceinline__ uint32_t smaddr(const void* p) {
    return (uint32_t)__cvta_generic_to_shared(p);
}
__device__ __forceinline__ void ldsm4(uint32_t addr, uint32_t& r0, uint32_t& r1,
                                      uint32_t& r2, uint32_t& r3) {
    asm volatile("ldmatrix.sync.aligned.m8n8.x4.shared.b16 {%0,%1,%2,%3}, [%4];"
                 : "=r"(r0), "=r"(r1), "=r"(r2), "=r"(r3) : "r"(addr));
}
__device__ __forceinline__ void ldsm4t(uint32_t addr, uint32_t& r0, uint32_t& r1,
                                       uint32_t& r2, uint32_t& r3) {
    asm volatile("ldmatrix.sync.aligned.m8n8.x4.trans.shared.b16 {%0,%1,%2,%3}, [%4];"
                 : "=r"(r0), "=r"(r1), "=r"(r2), "=r"(r3) : "r"(addr));
}
__device__ __forceinline__ void mma_bf16(float& c0, float& c1, float& c2, float& c3,
                                         uint32_t a0, uint32_t a1, uint32_t a2, uint32_t a3,
                                         uint32_t b0, uint32_t b1) {
    asm volatile("mma.sync.aligned.m16n8k16.row.col.f32.bf16.bf16.f32 "
                 "{%0,%1,%2,%3}, {%4,%5,%6,%7}, {%8,%9}, {%0,%1,%2,%3};"
                 : "+f"(c0), "+f"(c1), "+f"(c2), "+f"(c3)
                 : "r"(a0), "r"(a1), "r"(a2), "r"(a3), "r"(b0), "r"(b1));
}
__device__ __forceinline__ void cp16(uint32_t dst, const void* src) {
    asm volatile("cp.async.cg.shared.global [%0], [%1], 16;" :: "r"(dst), "l"(src));
}
__device__ __forceinline__ void cp_commit() { asm volatile("cp.async.commit_group;"); }
template <int N> __device__ __forceinline__ void cp_wait() {
    asm volatile("cp.async.wait_group %0;" :: "n"(N));
}

// ---------------------------------------------------------------------------
// smem layout
//   mainloop: stages[2] of { A[64m][72k] bf16 (9216 B) | B[64k][520n] bf16 (66560 B) }
//   epilogue (reuses stage memory): W2s[512k][40n] bf16 @0 | H2p[64][8][33] f32 @40960
// ---------------------------------------------------------------------------
static constexpr uint32_t A_STR_B  = 144;     // 72 elems * 2B
static constexpr uint32_t B_STR_B  = 1040;    // 520 elems * 2B
static constexpr uint32_t ABUF     = 0;
static constexpr uint32_t BBUF     = 9216;
static constexpr uint32_t STAGE_B  = 75776;   // 9216 + 66560
static constexpr uint32_t SMEM_TOTAL = 2 * STAGE_B;   // 151552
static constexpr uint32_t W2S_STR_B = 80;     // 40 elems * 2B
static constexpr uint32_t H2P_OFF   = 40960;  // after W2s (512*80 = 40960)

// ---------------------------------------------------------------------------
// kernel 0: convert W1/W2 fp32 -> bf16 device globals (layouts preserved)
// ---------------------------------------------------------------------------
__global__ void k_convert(const float* __restrict__ W1, const float* __restrict__ W2) {
    int g = blockIdx.x * blockDim.x + threadIdx.x;
    const int n1 = DIN * H1 / 4;
    const int n2 = H1 * H2 / 4;
    if (g < n1) {
        float4 v = reinterpret_cast<const float4*>(W1)[g];
        __nv_bfloat162* p = reinterpret_cast<__nv_bfloat162*>(g_w1b) + g * 2;
        p[0] = __floats2bfloat162_rn(v.x, v.y);
        p[1] = __floats2bfloat162_rn(v.z, v.w);
    } else if (g - n1 < n2) {
        int h = g - n1;
        float4 v = reinterpret_cast<const float4*>(W2)[h];
        __nv_bfloat162* p = reinterpret_cast<__nv_bfloat162*>(g_w2b) + h * 2;
        p[0] = __floats2bfloat162_rn(v.x, v.y);
        p[1] = __floats2bfloat162_rn(v.z, v.w);
    }
}

// ---------------------------------------------------------------------------
// fused MLP: 1024 CTAs x 512 threads, M=64 N=512 per CTA, k-slab 64, 2 stages
//   16 warps as 2(m) x 8(n): warp tile 32 rows x 64 cols
// ---------------------------------------------------------------------------
__global__ void __launch_bounds__(512, 1)
k_fused(const float* __restrict__ X, const float* __restrict__ b1,
        const float* __restrict__ b2, const float* __restrict__ W3,
        const float* __restrict__ b3) {
    extern __shared__ char smem[];
    const uint32_t sb = smaddr(smem);
    const int tid  = threadIdx.x;
    const int lane = tid & 31;
    const int wid  = tid >> 5;
    const int wm   = wid >> 3;     // 0..1 -> rows wm*32..+31
    const int wn   = wid & 7;      // 0..7 -> cols wn*64..+63
    const int m0   = blockIdx.x * 64;

    const int lk   = lane & 15;
    const int lhi8 = (lane & 16) ? 8 : 0;

    // A-load indices (per thread): row m, k-segment of 8 floats
    const int am   = tid >> 3;     // 0..63
    const int aks  = tid & 7;      // 0..7

    float c[2][8][4];
    #pragma unroll
    for (int mf = 0; mf < 2; mf++)
        #pragma unroll
        for (int t = 0; t < 8; t++)
            #pragma unroll
            for (int q = 0; q < 4; q++) c[mf][t][q] = 0.f;

    // ---- B slab loader: 4096 cp16 / 512 threads = 8 each ----
    auto loadB = [&](int k0, uint32_t stage_off) {
        #pragma unroll
        for (int j = 0; j < 8; j++) {
            int i = tid + 512 * j;
            int kr = i >> 6, seg = i & 63;
            cp16(sb + stage_off + BBUF + (uint32_t)kr * B_STR_B + (uint32_t)seg * 16,
                 g_w1b + (size_t)(k0 + kr) * H1 + seg * 8);
        }
    };
    // ---- A slab: LDG fp32 -> regs ----
    float4 xa, xb;
    auto loadA_regs = [&](int k0) {
        const float4* xp = reinterpret_cast<const float4*>(
            X + (size_t)(m0 + am) * DIN + k0 + aks * 8);
        xa = xp[0]; xb = xp[1];
    };
    // ---- A slab: convert + STS ----
    auto stsA = [&](uint32_t stage_off) {
        __nv_bfloat162 p0 = __floats2bfloat162_rn(xa.x, xa.y);
        __nv_bfloat162 p1 = __floats2bfloat162_rn(xa.z, xa.w);
        __nv_bfloat162 p2 = __floats2bfloat162_rn(xb.x, xb.y);
        __nv_bfloat162 p3 = __floats2bfloat162_rn(xb.z, xb.w);
        uint4 v = make_uint4(*(uint32_t*)&p0, *(uint32_t*)&p1,
                             *(uint32_t*)&p2, *(uint32_t*)&p3);
        *reinterpret_cast<uint4*>(smem + stage_off + ABUF +
                                  (uint32_t)am * A_STR_B + (uint32_t)aks * 16) = v;
    };

    // ---- prologue: slab 0 ----
    loadB(0, 0);
    cp_commit();
    loadA_regs(0);
    stsA(0);
    cp_wait<0>();
    __syncthreads();

    // ---- mainloop: 16 k-slabs of 64 ----
    for (int ks = 0; ks < 16; ks++) {
        const uint32_t cur = (uint32_t)(ks & 1) * STAGE_B;
        const uint32_t nxt = cur ^ STAGE_B;
        if (ks < 15) {
            loadB((ks + 1) * 64, nxt);
            cp_commit();
            loadA_regs((ks + 1) * 64);
        }

        const uint32_t abase = sb + cur + ABUF +
            (uint32_t)(wm * 32 + lk) * A_STR_B + (uint32_t)lhi8 * 2;
        const uint32_t bbase = sb + cur + BBUF +
            (uint32_t)lk * B_STR_B + (uint32_t)(wn * 64 + lhi8) * 2;

        #pragma unroll
        for (int st = 0; st < 4; st++) {
            uint32_t bb[4][4];
            #pragma unroll
            for (int p = 0; p < 4; p++)
                ldsm4t(bbase + (uint32_t)st * 16 * B_STR_B + (uint32_t)p * 32,
                       bb[p][0], bb[p][1], bb[p][2], bb[p][3]);
            #pragma unroll
            for (int mf = 0; mf < 2; mf++) {
                uint32_t a0, a1, a2, a3;
                ldsm4(abase + (uint32_t)mf * 16 * A_STR_B + (uint32_t)st * 32,
                      a0, a1, a2, a3);
                #pragma unroll
                for (int t = 0; t < 8; t++)
                    mma_bf16(c[mf][t][0], c[mf][t][1], c[mf][t][2], c[mf][t][3],
                             a0, a1, a2, a3,
                             bb[t >> 1][(t & 1) * 2], bb[t >> 1][(t & 1) * 2 + 1]);
            }
        }

        if (ks < 15) {
            stsA(nxt);
            cp_wait<0>();
        }
        __syncthreads();
    }

    // =======================================================================
    // epilogue: layer2 (mma) + layer3 + sigmoid.  Stage memory is dead.
    // =======================================================================
    // W2s[512][40] bf16 at smem+0 via cp.async
    {
        #pragma unroll
        for (int j = 0; j < 4; j++) {
            int i = tid + 512 * j;          // 0..2047
            int kr = i >> 2, seg = i & 3;
            cp16(sb + (uint32_t)kr * W2S_STR_B + (uint32_t)seg * 16,
                 g_w2b + (size_t)kr * H2 + seg * 8);
        }
        cp_commit();
        cp_wait<0>();
    }

    // layer-1 bias per owned column pair
    float2 bias[8];
    #pragma unroll
    for (int t = 0; t < 8; t++)
        bias[t] = *reinterpret_cast<const float2*>(b1 + wn * 64 + t * 8 + (lane & 3) * 2);

    // bias + relu + pack c-frags -> layer-2 A-frags (proven R1 mapping)
    uint32_t a2f[2][4][4];
    #pragma unroll
    for (int mf = 0; mf < 2; mf++) {
        #pragma unroll
        for (int s = 0; s < 4; s++) {
            const int t0 = 2 * s, t1 = 2 * s + 1;
            __nv_bfloat162 h;
            h = __floats2bfloat162_rn(fmaxf(c[mf][t0][0] + bias[t0].x, 0.f),
                                      fmaxf(c[mf][t0][1] + bias[t0].y, 0.f));
            a2f[mf][s][0] = *(uint32_t*)&h;
            h = __floats2bfloat162_rn(fmaxf(c[mf][t0][2] + bias[t0].x, 0.f),
                                      fmaxf(c[mf][t0][3] + bias[t0].y, 0.f));
            a2f[mf][s][1] = *(uint32_t*)&h;
            h = __floats2bfloat162_rn(fmaxf(c[mf][t1][0] + bias[t1].x, 0.f),
                                      fmaxf(c[mf][t1][1] + bias[t1].y, 0.f));
            a2f[mf][s][2] = *(uint32_t*)&h;
            h = __floats2bfloat162_rn(fmaxf(c[mf][t1][2] + bias[t1].x, 0.f),
                                      fmaxf(c[mf][t1][3] + bias[t1].y, 0.f));
            a2f[mf][s][3] = *(uint32_t*)&h;
        }
    }
    __syncthreads();   // all threads' cp.async W2 done (each waited own group)

    // layer-2 mma: this warp's k-slice = cols wn*64..+63 -> partial h2 [32 x 32]
    float d2[2][4][4];
    #pragma unroll
    for (int mf = 0; mf < 2; mf++)
        #pragma unroll
        for (int nf = 0; nf < 4; nf++)
            #pragma unroll
            for (int q = 0; q < 4; q++) d2[mf][nf][q] = 0.f;

    #pragma unroll
    for (int s = 0; s < 4; s++) {
        uint32_t wb[2][4];
        #pragma unroll
        for (int nh = 0; nh < 2; nh++)
            ldsm4t(sb + (uint32_t)(wn * 64 + s * 16 + lk) * W2S_STR_B +
                       (uint32_t)(lhi8 + nh * 16) * 2,
                   wb[nh][0], wb[nh][1], wb[nh][2], wb[nh][3]);
        #pragma unroll
        for (int mf = 0; mf < 2; mf++)
            #pragma unroll
            for (int nf = 0; nf < 4; nf++)
                mma_bf16(d2[mf][nf][0], d2[mf][nf][1], d2[mf][nf][2], d2[mf][nf][3],
                         a2f[mf][s][0], a2f[mf][s][1], a2f[mf][s][2], a2f[mf][s][3],
                         wb[nf >> 1][(nf & 1) * 2], wb[nf >> 1][(nf & 1) * 2 + 1]);
    }

    // store partials: H2p[row][wn][col], row-major [64][8][33] f32
    float* H2p = reinterpret_cast<float*>(smem + H2P_OFF);
    #pragma unroll
    for (int mf = 0; mf < 2; mf++)
        #pragma unroll
        for (int nf = 0; nf < 4; nf++)
            #pragma unroll
            for (int q = 0; q < 4; q++) {
                int row = wm * 32 + mf * 16 + (lane >> 2) + ((q >= 2) ? 8 : 0);
                int col = nf * 8 + (lane & 3) * 2 + (q & 1);
                H2p[(row * 8 + wn) * 33 + col] = d2[mf][nf][q];
            }
    __syncthreads();

    // layer 3 + sigmoid
    if (tid < 64) {
        float acc = b3[0];
        #pragma unroll
        for (int j = 0; j < H2; j++) {
            float s = 0.f;
            #pragma unroll
            for (int w = 0; w < 8; w++) s += H2p[(tid * 8 + w) * 33 + j];
            acc += (s + b2[j]) * W3[j];
        }
        g_logits[m0 + tid] = 1.0f / (1.0f + expf(-acc));
    }
}

// ---------------------------------------------------------------------------
// per-sample masked bitonic sort + top-k mean (exact ref semantics)
// ---------------------------------------------------------------------------
__global__ void k_topk(const int* __restrict__ seq_len, float* __restrict__ out) {
    __shared__ float v[Tn];
    __shared__ float red[256];
    const int b = blockIdx.x;
    const int tid = threadIdx.x;
    const int sl = seq_len[b];
    const int k = sl / 16 + 1;

    for (int i = tid; i < Tn; i += 256)
        v[i] = (i < sl) ? g_logits[b * Tn + i] : -1.0f;
    __syncthreads();

    for (int kk = 2; kk <= Tn; kk <<= 1) {
        for (int j = kk >> 1; j > 0; j >>= 1) {
            for (int i = tid; i < Tn; i += 256) {
                int ixj = i ^ j;
                if (ixj > i) {
                    float a = v[i], cc = v[ixj];
                    bool up = ((i & kk) == 0);
                    if ((a > cc) == up) { v[i] = cc; v[ixj] = a; }
                }
            }
            __syncthreads();
        }
    }
    float s = 0.f;
    for (int i = Tn - k + tid; i < Tn; i += 256) s += v[i];
    red[tid] = s;
    __syncthreads();
    for (int off = 128; off > 0; off >>= 1) {
        if (tid < off) red[tid] += red[tid + off];
        __syncthreads();
    }
    if (tid == 0) out[b] = red[0] / (float)k;
}

// ---------------------------------------------------------------------------
extern "C" void kernel_launch(void* const* d_in, const int* in_sizes, int n_in,
                              void* d_out, int out_size) {
    const float* X   = (const float*)d_in[0];
    const float* W1  = (const float*)d_in[1];
    const float* b1  = (const float*)d_in[2];
    const float* W2  = (const float*)d_in[3];
    const float* b2  = (const float*)d_in[4];
    const float* W3  = (const float*)d_in[5];
    const float* b3  = (const float*)d_in[6];
    const int*   seq = (const int*)d_in[7];
    float* out = (float*)d_out;

    k_convert<<<(DIN * H1 / 4 + H1 * H2 / 4 + 255) / 256, 256>>>(W1, W2);

    cudaFuncSetAttribute(k_fused, cudaFuncAttributeMaxDynamicSharedMemorySize, SMEM_TOTAL);
    k_fused<<<Mrows / 64, 512, SMEM_TOTAL>>>(X, b1, b2, W3, b3);

    k_topk<<<Bn, 256>>>(seq, out);
}